// round 6
// baseline (speedup 1.0000x reference)
#include <cuda_runtime.h>

// MPSLayer, fused single kernel.
//   out[b,o]  = s[b]*v[o] + bias[o]
//   s[b]      = prod_n x[b,n]
//   u         = ones^T @ core_0 @ ... @ core_255
//   Psum[r,o] = sum_l proj[r,l,o]
//   v[o]      = sum_r u[r]*Psum[r,o]
// Tree: 64 blocks ∏4 cores -> D ; blocks {0,4,..,60} ∏4 D -> E (own D kept in
// regs, siblings via per-flag cp.async pipe) ; block 0: 16-step vector chain
// consuming E_n in order through a cp.async ring.

#define DD      32
#define N_IN    256
#define BATCH   1024
#define OUT_DIM 512

__device__ __align__(16) float g_D[64 * 1024];
__device__ __align__(16) float g_E[16 * 1024];
__device__ __align__(16) float g_s[BATCH];
__device__ __align__(16) float g_Psum[DD * OUT_DIM];
__device__ __align__(16) float g_v[OUT_DIM];

__device__ int g_flag_D[64];   // per-D completion (only blk&3!=0 used)
__device__ int g_flag_E[16];   // per-E completion (1..15 used)
__device__ int g_cnt_P, g_cnt_S, g_flag_v, g_cnt_done;

// ---- sync primitives --------------------------------------------------------
__device__ __forceinline__ int ld_acq(const int* p) {
    int v;
    asm volatile("ld.acquire.gpu.global.b32 %0, [%1];" : "=r"(v) : "l"(p) : "memory");
    return v;
}
__device__ __forceinline__ void red_rel_add(int* p, int v) {
    asm volatile("red.release.gpu.global.add.s32 [%0], %1;" :: "l"(p), "r"(v) : "memory");
}
__device__ __forceinline__ void st_relaxed(int* p, int v) {
    asm volatile("st.relaxed.gpu.global.b32 [%0], %1;" :: "l"(p), "r"(v) : "memory");
}
__device__ __forceinline__ void spin_ge(int* cnt, int target) {
    if (threadIdx.x == 0) { while (ld_acq(cnt) < target) { } }
    __syncthreads();
}
__device__ __forceinline__ void spin_warp(int* flag) {
    if ((threadIdx.x & 31) == 0) { while (ld_acq(flag) < 1) { } }
    __syncwarp();
}

// ---- cp.async ---------------------------------------------------------------
__device__ __forceinline__ void cpa16(unsigned dst, const float* src) {
    asm volatile("cp.async.ca.shared.global [%0], [%1], 16;" :: "r"(dst), "l"(src));
}
#define CP_COMMIT() asm volatile("cp.async.commit_group;" ::: "memory")
#define CP_WAIT(n)  asm volatile("cp.async.wait_group %0;" :: "n"(n) : "memory")

// ---------------------------------------------------------------------------
// Register-resident 32x32 step: thread owns P[l][4q..4q+3] (l=tid>>3, q=tid&7);
// returns P @ B(smem). Row values gathered via shfl within the 8-lane row group.
// ---------------------------------------------------------------------------
__device__ __forceinline__ float4 mm_step_reg(float4 p, const float4* __restrict__ B4,
                                              int lane, int q) {
    float4 acc = make_float4(0.f, 0.f, 0.f, 0.f);
    int grp = lane & 24;
    #pragma unroll
    for (int j = 0; j < 8; ++j) {
        float a; float4 b;
        a = __shfl_sync(0xffffffffu, p.x, grp + j);
        b = B4[(4 * j + 0) * 8 + q];
        acc.x = fmaf(a, b.x, acc.x); acc.y = fmaf(a, b.y, acc.y);
        acc.z = fmaf(a, b.z, acc.z); acc.w = fmaf(a, b.w, acc.w);
        a = __shfl_sync(0xffffffffu, p.y, grp + j);
        b = B4[(4 * j + 1) * 8 + q];
        acc.x = fmaf(a, b.x, acc.x); acc.y = fmaf(a, b.y, acc.y);
        acc.z = fmaf(a, b.z, acc.z); acc.w = fmaf(a, b.w, acc.w);
        a = __shfl_sync(0xffffffffu, p.z, grp + j);
        b = B4[(4 * j + 2) * 8 + q];
        acc.x = fmaf(a, b.x, acc.x); acc.y = fmaf(a, b.y, acc.y);
        acc.z = fmaf(a, b.z, acc.z); acc.w = fmaf(a, b.w, acc.w);
        a = __shfl_sync(0xffffffffu, p.w, grp + j);
        b = B4[(4 * j + 3) * 8 + q];
        acc.x = fmaf(a, b.x, acc.x); acc.y = fmaf(a, b.y, acc.y);
        acc.z = fmaf(a, b.z, acc.z); acc.w = fmaf(a, b.w, acc.w);
    }
    return acc;
}

// Product of 4 consecutive 32x32 matrices (global src), result in regs.
__device__ __forceinline__ float4 mm_chain4_reg(const float4* __restrict__ src4,
                                                float4* sB0, float4* sB1) {
    int tid = threadIdx.x, lane = tid & 31, q = tid & 7;
    float4 p  = src4[tid];
    float4 b1 = src4[256 + tid];
    float4 b2 = src4[512 + tid];
    float4 b3 = src4[768 + tid];
    sB0[tid] = b1; __syncthreads();
    p = mm_step_reg(p, sB0, lane, q);
    sB1[tid] = b2; __syncthreads();
    p = mm_step_reg(p, sB1, lane, q);
    sB0[tid] = b3; __syncthreads();
    p = mm_step_reg(p, sB0, lane, q);
    return p;
}

// one vector-chain step: u <- u @ D (D at d, row-major), lane owns column lane
__device__ __forceinline__ float chain_step_smem(float u, const float* __restrict__ d,
                                                 int lane) {
    float a0 = 0.f, a1 = 0.f, a2 = 0.f, a3 = 0.f;
    #pragma unroll
    for (int k = 0; k < DD; k += 4) {
        a0 = fmaf(__shfl_sync(0xffffffffu, u, k + 0), d[(k + 0) * DD + lane], a0);
        a1 = fmaf(__shfl_sync(0xffffffffu, u, k + 1), d[(k + 1) * DD + lane], a1);
        a2 = fmaf(__shfl_sync(0xffffffffu, u, k + 2), d[(k + 2) * DD + lane], a2);
        a3 = fmaf(__shfl_sync(0xffffffffu, u, k + 3), d[(k + 3) * DD + lane], a3);
    }
    return (a0 + a1) + (a2 + a3);
}

// ---------------------------------------------------------------------------
__global__ void __launch_bounds__(256, 2) fused_mps(
    const float* __restrict__ x, const float* __restrict__ cores,
    const float* __restrict__ proj, const float* __restrict__ bias,
    float* __restrict__ out) {

    __shared__ __align__(16) float sm[4 * 1024];   // 4 stages x 4KB
    __shared__ float sU[DD];
    int tid = threadIdx.x;
    int blk = blockIdx.x;
    int lane = tid & 31;
    int q = tid & 7;

    int o4 = tid & 127;
    float4 bi = reinterpret_cast<const float4*>(bias)[o4];

    float4* stg[4] = {
        reinterpret_cast<float4*>(sm),
        reinterpret_cast<float4*>(sm + 1024),
        reinterpret_cast<float4*>(sm + 2048),
        reinterpret_cast<float4*>(sm + 3072) };
    unsigned smb = (unsigned)__cvta_generic_to_shared(sm);

    if (blk < 64) {
        // ---- level 1: product of 4 cores (result in regs)
        float4 p = mm_chain4_reg(
            reinterpret_cast<const float4*>(cores) + (size_t)blk * 1024,
            stg[0], stg[1]);

        if (blk & 3) {
            // sibling: publish D
            reinterpret_cast<float4*>(g_D)[blk * 256 + tid] = p;
            __syncthreads();
            if (tid == 0) red_rel_add(&g_flag_D[blk], 1);
        } else {
            // ---- level 2 on blk = 4g: E = p @ D1 @ D2 @ D3, siblings via cp.async
            int g = blk >> 2;
            spin_ge(&g_flag_D[blk + 1], 1);
            cpa16(smb + 1 * 4096 + tid * 16, g_D + (blk + 1) * 1024 + tid * 4);
            CP_COMMIT();
            spin_ge(&g_flag_D[blk + 2], 1);
            cpa16(smb + 2 * 4096 + tid * 16, g_D + (blk + 2) * 1024 + tid * 4);
            CP_COMMIT();
            CP_WAIT(1); __syncthreads();
            p = mm_step_reg(p, stg[1], lane, q);
            spin_ge(&g_flag_D[blk + 3], 1);
            cpa16(smb + 3 * 4096 + tid * 16, g_D + (blk + 3) * 1024 + tid * 4);
            CP_COMMIT();
            CP_WAIT(1); __syncthreads();
            p = mm_step_reg(p, stg[2], lane, q);
            CP_WAIT(0); __syncthreads();
            p = mm_step_reg(p, stg[3], lane, q);
            if (tid == 0) {
                st_relaxed(&g_flag_D[blk + 1], 0);
                st_relaxed(&g_flag_D[blk + 2], 0);
                st_relaxed(&g_flag_D[blk + 3], 0);
            }
            if (g > 0) {
                reinterpret_cast<float4*>(g_E)[g * 256 + tid] = p;
                __syncthreads();
                if (tid == 0) red_rel_add(&g_flag_E[g], 1);
            } else {
                // E0 consumed only locally: place into ring stage 0
                __syncthreads();          // stage reads above complete
                stg[0][tid] = p;
                __syncthreads();
            }
        }

        if (blk == 0) {
            // Psum ready early: sync, reset, prefetch columns into regs
            spin_ge(&g_cnt_P, 64);
            if (tid == 0) st_relaxed(&g_cnt_P, 0);
            float pc0[DD], pc1[DD];
            #pragma unroll
            for (int r = 0; r < DD; ++r) pc0[r] = g_Psum[r * OUT_DIM + tid];
            #pragma unroll
            for (int r = 0; r < DD; ++r) pc1[r] = g_Psum[r * OUT_DIM + tid + 256];

            if (tid < DD) {
                // prime stages 1..3 (warp 0 only; per-E flags)
                #pragma unroll
                for (int m = 1; m <= 3; ++m) {
                    spin_warp(&g_flag_E[m]);
                    const float* s = g_E + m * 1024 + lane * 4;
                    unsigned d = smb + (unsigned)(m & 3) * 4096 + lane * 16;
                    #pragma unroll
                    for (int i = 0; i < 8; ++i) cpa16(d + i * 512, s + i * 128);
                    CP_COMMIT();
                }
                float u = 1.f;
                #pragma unroll
                for (int n = 0; n < 16; ++n) {
                    if (n >= 1) {
                        if (n <= 12)      CP_WAIT(3);
                        else if (n == 13) CP_WAIT(2);
                        else if (n == 14) CP_WAIT(1);
                        else              CP_WAIT(0);
                        __syncwarp();
                    }
                    u = chain_step_smem(u, sm + (n & 3) * 1024, lane);
                    int m = n + 4;
                    if (m < 16) {      // refill the slot just freed
                        spin_warp(&g_flag_E[m]);
                        const float* s = g_E + m * 1024 + lane * 4;
                        unsigned d = smb + (unsigned)(m & 3) * 4096 + lane * 16;
                        #pragma unroll
                        for (int i = 0; i < 8; ++i) cpa16(d + i * 512, s + i * 128);
                        CP_COMMIT();
                    }
                }
                sU[lane] = u;
            }
            __syncthreads();
            // v = u^T Psum (from prefetched registers)
            float a0 = 0.f, a1 = 0.f;
            #pragma unroll
            for (int r = 0; r < DD; ++r) {
                float ur = sU[r];
                a0 = fmaf(ur, pc0[r], a0);
                a1 = fmaf(ur, pc1[r], a1);
            }
            g_v[tid]       = a0;
            g_v[tid + 256] = a1;
            __syncthreads();
            if (tid == 0) {
                #pragma unroll
                for (int m = 1; m < 16; ++m) st_relaxed(&g_flag_E[m], 0);
                red_rel_add(&g_flag_v, 1);
            }
        }
    } else if (blk < 192) {
        // ---- s[b]: 8 rows per block, one warp per row
        int w = tid >> 5;
        int b = (blk - 64) * 8 + w;
        const float* row = x + (size_t)b * N_IN;
        float pr = 1.f;
        #pragma unroll
        for (int i = 0; i < N_IN / DD; ++i) pr *= row[lane + i * DD];
        #pragma unroll
        for (int off = 16; off; off >>= 1)
            pr *= __shfl_xor_sync(0xffffffffu, pr, off);
        if (lane == 0) g_s[b] = pr;
        __syncthreads();
        if (tid == 0) red_rel_add(&g_cnt_S, 1);
    } else {
        // ---- Psum[r, half]
        int p = blk - 192;
        int r = p >> 1;
        int o = (p & 1) * 256 + tid;
        const float* base = proj + (size_t)r * DD * OUT_DIM + o;
        float acc = 0.f;
        #pragma unroll
        for (int l = 0; l < DD; ++l) acc += base[l * OUT_DIM];
        g_Psum[r * OUT_DIM + o] = acc;
        __syncthreads();
        if (tid == 0) red_rel_add(&g_cnt_P, 1);
    }

    // ---- epilogue: out[b,o] = s[b]*v[o] + bias[o] ---------------------------
    int sub = tid >> 7;
    int b0 = blk * 4;
    spin_ge(&g_cnt_S, 128);                 // s ready first; prefetch while v cooks
    float s0 = g_s[b0 + sub];
    float s1 = g_s[b0 + 2 + sub];
    spin_ge(&g_flag_v, 1);
    float4 v = reinterpret_cast<const float4*>(g_v)[o4];
    float4* out4 = reinterpret_cast<float4*>(out);
    float4 o0, o1;
    o0.x = fmaf(s0, v.x, bi.x); o0.y = fmaf(s0, v.y, bi.y);
    o0.z = fmaf(s0, v.z, bi.z); o0.w = fmaf(s0, v.w, bi.w);
    o1.x = fmaf(s1, v.x, bi.x); o1.y = fmaf(s1, v.y, bi.y);
    o1.z = fmaf(s1, v.z, bi.z); o1.w = fmaf(s1, v.w, bi.w);
    out4[(size_t)(b0 + sub) * 128 + o4]     = o0;
    out4[(size_t)(b0 + 2 + sub) * 128 + o4] = o1;

    // ---- last block resets shared flags for next graph replay --------------
    __syncthreads();
    if (tid == 0) {
        int old = atomicAdd(&g_cnt_done, 1);
        if (old == 255) {
            st_relaxed(&g_cnt_S, 0);
            st_relaxed(&g_flag_v, 0);
            st_relaxed(&g_cnt_done, 0);
        }
    }
}

// ---------------------------------------------------------------------------
extern "C" void kernel_launch(void* const* d_in, const int* in_sizes, int n_in,
                              void* d_out, int out_size) {
    const float* x     = (const float*)d_in[0];
    const float* cores = (const float*)d_in[1];
    const float* proj  = (const float*)d_in[2];
    const float* bias  = (const float*)d_in[3];
    float* out = (float*)d_out;

    fused_mps<<<256, 256>>>(x, cores, proj, bias, out);
}

// round 7
// speedup vs baseline: 1.2924x; 1.2924x over previous
#include <cuda_runtime.h>

// MPSLayer, fused single kernel. Round-5 compute core + decontended sync:
// no shared counters with >1 poller, no end-of-kernel reset storm.
//   out[b,o]  = s[b]*v[o] + bias[o]
//   s[b]      = prod_n x[b,n]        (computed privately per epilogue block)
//   u         = ones^T @ core_0 @ ... @ core_255
//   Psum[r,o] = sum_l proj[r,l,o]
//   v[o]      = sum_r u[r]*Psum[r,o]
// Tree: 64 blocks ∏4 cores -> D ; blocks 0..15 ∏4 D -> E ;
//       block 0: 16-step vector chain via cp.async ring -> u -> v.
// Grid 128 x 256 (blocks 64..127 compute Psum); all co-resident.

#define DD      32
#define N_IN    256
#define BATCH   1024
#define OUT_DIM 512

__device__ __align__(16) float g_D[64 * 1024];
__device__ __align__(16) float g_E[16 * 1024];
__device__ __align__(16) float g_Psum[DD * OUT_DIM];
__device__ __align__(16) float g_v[OUT_DIM];

__device__ int g_cnt_D4[16];     // 4 producers, 1 poller each
__device__ int g_cnt_E;          // 15 producers, 1 poller (block 0)
__device__ int g_cnt_P;          // 64 producers, 1 poller (block 0)
__device__ int g_flag_v_p[128];  // private: 1 producer-thread, 1 poller each

// ---- sync primitives --------------------------------------------------------
__device__ __forceinline__ int ld_acq(const int* p) {
    int v;
    asm volatile("ld.acquire.gpu.global.b32 %0, [%1];" : "=r"(v) : "l"(p) : "memory");
    return v;
}
__device__ __forceinline__ int ld_rlx(const int* p) {
    int v;
    asm volatile("ld.relaxed.gpu.global.b32 %0, [%1];" : "=r"(v) : "l"(p) : "memory");
    return v;
}
__device__ __forceinline__ void red_rel_add(int* p, int v) {
    asm volatile("red.release.gpu.global.add.s32 [%0], %1;" :: "l"(p), "r"(v) : "memory");
}
__device__ __forceinline__ void st_relaxed(int* p, int v) {
    asm volatile("st.relaxed.gpu.global.b32 [%0], %1;" :: "l"(p), "r"(v) : "memory");
}
__device__ __forceinline__ void spin_ge(int* cnt, int target) {
    if (threadIdx.x == 0) {
        while (ld_rlx(cnt) < target) { }
        (void)ld_acq(cnt);
    }
    __syncthreads();
}

// ---- cp.async ---------------------------------------------------------------
__device__ __forceinline__ void cpa16(unsigned dst, const float* src) {
    asm volatile("cp.async.ca.shared.global [%0], [%1], 16;" :: "r"(dst), "l"(src));
}
#define CP_COMMIT() asm volatile("cp.async.commit_group;" ::: "memory")
#define CP_WAIT(n)  asm volatile("cp.async.wait_group %0;" :: "n"(n) : "memory")

// ---------------------------------------------------------------------------
// Register-resident 32x32 step: thread owns P[l][4q..4q+3] (l=tid>>3, q=tid&7);
// returns P @ B(smem). Row values gathered by shfl within the 8-lane row group.
// ---------------------------------------------------------------------------
__device__ __forceinline__ float4 mm_step_reg(float4 p, const float4* __restrict__ B4,
                                              int lane, int q) {
    float4 acc = make_float4(0.f, 0.f, 0.f, 0.f);
    int grp = lane & 24;
    #pragma unroll
    for (int j = 0; j < 8; ++j) {
        float a; float4 b;
        a = __shfl_sync(0xffffffffu, p.x, grp + j);
        b = B4[(4 * j + 0) * 8 + q];
        acc.x = fmaf(a, b.x, acc.x); acc.y = fmaf(a, b.y, acc.y);
        acc.z = fmaf(a, b.z, acc.z); acc.w = fmaf(a, b.w, acc.w);
        a = __shfl_sync(0xffffffffu, p.y, grp + j);
        b = B4[(4 * j + 1) * 8 + q];
        acc.x = fmaf(a, b.x, acc.x); acc.y = fmaf(a, b.y, acc.y);
        acc.z = fmaf(a, b.z, acc.z); acc.w = fmaf(a, b.w, acc.w);
        a = __shfl_sync(0xffffffffu, p.z, grp + j);
        b = B4[(4 * j + 2) * 8 + q];
        acc.x = fmaf(a, b.x, acc.x); acc.y = fmaf(a, b.y, acc.y);
        acc.z = fmaf(a, b.z, acc.z); acc.w = fmaf(a, b.w, acc.w);
        a = __shfl_sync(0xffffffffu, p.w, grp + j);
        b = B4[(4 * j + 3) * 8 + q];
        acc.x = fmaf(a, b.x, acc.x); acc.y = fmaf(a, b.y, acc.y);
        acc.z = fmaf(a, b.z, acc.z); acc.w = fmaf(a, b.w, acc.w);
    }
    return acc;
}

// Product of 4 consecutive 32x32 matrices (global src), result in regs.
__device__ __forceinline__ float4 mm_chain4_reg(const float4* __restrict__ src4,
                                                float4* sB0, float4* sB1) {
    int tid = threadIdx.x, lane = tid & 31, q = tid & 7;
    float4 p  = src4[tid];
    float4 b1 = src4[256 + tid];
    float4 b2 = src4[512 + tid];
    float4 b3 = src4[768 + tid];
    sB0[tid] = b1; __syncthreads();
    p = mm_step_reg(p, sB0, lane, q);
    sB1[tid] = b2; __syncthreads();
    p = mm_step_reg(p, sB1, lane, q);
    sB0[tid] = b3; __syncthreads();
    p = mm_step_reg(p, sB0, lane, q);
    return p;
}

// one vector-chain step: u <- u @ D (row-major at d), lane owns column lane
__device__ __forceinline__ float chain_step_smem(float u, const float* __restrict__ d,
                                                 int lane) {
    float a0 = 0.f, a1 = 0.f, a2 = 0.f, a3 = 0.f;
    #pragma unroll
    for (int k = 0; k < DD; k += 4) {
        a0 = fmaf(__shfl_sync(0xffffffffu, u, k + 0), d[(k + 0) * DD + lane], a0);
        a1 = fmaf(__shfl_sync(0xffffffffu, u, k + 1), d[(k + 1) * DD + lane], a1);
        a2 = fmaf(__shfl_sync(0xffffffffu, u, k + 2), d[(k + 2) * DD + lane], a2);
        a3 = fmaf(__shfl_sync(0xffffffffu, u, k + 3), d[(k + 3) * DD + lane], a3);
    }
    return (a0 + a1) + (a2 + a3);
}

// ---------------------------------------------------------------------------
__global__ void __launch_bounds__(256) fused_mps(
    const float* __restrict__ x, const float* __restrict__ cores,
    const float* __restrict__ proj, const float* __restrict__ bias,
    float* __restrict__ out) {

    __shared__ __align__(16) float sm[4 * 1024];   // 4 stages x 4KB
    __shared__ float sU[DD];
    __shared__ float sS[8];
    int tid = threadIdx.x;
    int blk = blockIdx.x;
    int lane = tid & 31;
    int w = tid >> 5;

    // ---- entry prefetches (independent of all phases) -----------------------
    int o4 = tid & 127;
    float4 bi = reinterpret_cast<const float4*>(bias)[o4];
    // x rows for this block's epilogue s-values: row = blk*8 + w
    const float4* x4 = reinterpret_cast<const float4*>(x);
    int xrow = blk * 8 + w;
    float4 xa = x4[xrow * 64 + lane];
    float4 xb = x4[xrow * 64 + 32 + lane];

    float4* stg0 = reinterpret_cast<float4*>(sm);
    float4* stg1 = reinterpret_cast<float4*>(sm + 1024);
    unsigned smb = (unsigned)__cvta_generic_to_shared(sm);

    if (blk < 64) {
        // ---- level 1: D[blk] = product of 4 cores (result in regs)
        float4 p = mm_chain4_reg(
            reinterpret_cast<const float4*>(cores) + (size_t)blk * 1024, stg0, stg1);
        reinterpret_cast<float4*>(g_D)[blk * 256 + tid] = p;
        __syncthreads();
        if (tid == 0) red_rel_add(&g_cnt_D4[blk >> 2], 1);

        if (blk < 16) {
            // ---- level 2: E[blk] = D[4blk] @ .. @ D[4blk+3]
            spin_ge(&g_cnt_D4[blk], 4);
            if (tid == 0) st_relaxed(&g_cnt_D4[blk], 0);
            float4 e = mm_chain4_reg(
                reinterpret_cast<const float4*>(g_D) + (size_t)blk * 1024, stg0, stg1);
            if (blk > 0) {
                reinterpret_cast<float4*>(g_E)[blk * 256 + tid] = e;
                __syncthreads();
                if (tid == 0) red_rel_add(&g_cnt_E, 1);
            } else {
                __syncthreads();           // mm reads of stage 0 complete
                stg0[tid] = e;             // E0 straight into ring stage 0
            }
        }
        if (blk == 0) {
            // Psum ready early: sync + prefetch its columns into registers
            spin_ge(&g_cnt_P, 64);
            if (tid == 0) st_relaxed(&g_cnt_P, 0);
            float pc0[DD], pc1[DD];
            #pragma unroll
            for (int r = 0; r < DD; ++r) pc0[r] = g_Psum[r * OUT_DIM + tid];
            #pragma unroll
            for (int r = 0; r < DD; ++r) pc1[r] = g_Psum[r * OUT_DIM + tid + 256];

            spin_ge(&g_cnt_E, 15);
            if (tid == 0) st_relaxed(&g_cnt_E, 0);

            if (tid < DD) {                 // warp 0: vector chain
                // prime ring stages 1..3
                #pragma unroll
                for (int m = 1; m <= 3; ++m) {
                    const float* s = g_E + m * 1024 + lane * 4;
                    unsigned d = smb + (unsigned)(m & 3) * 4096 + lane * 16;
                    #pragma unroll
                    for (int i = 0; i < 8; ++i) cpa16(d + i * 512, s + i * 128);
                    CP_COMMIT();
                }
                float u = 1.f;
                #pragma unroll
                for (int n = 0; n < 16; ++n) {
                    if (n >= 1) {
                        if (n <= 13)      CP_WAIT(2);
                        else if (n == 14) CP_WAIT(1);
                        else              CP_WAIT(0);
                        __syncwarp();
                    }
                    int m = n + 3;
                    if (m >= 4 && m < 16) {     // refill freed slot
                        const float* s = g_E + m * 1024 + lane * 4;
                        unsigned d = smb + (unsigned)(m & 3) * 4096 + lane * 16;
                        #pragma unroll
                        for (int i = 0; i < 8; ++i) cpa16(d + i * 512, s + i * 128);
                        CP_COMMIT();
                    }
                    u = chain_step_smem(u, sm + (n & 3) * 1024, lane);
                }
                sU[lane] = u;
            }
            __syncthreads();
            // v = u^T Psum (from prefetched registers)
            float a0 = 0.f, a1 = 0.f;
            #pragma unroll
            for (int r = 0; r < DD; ++r) {
                float ur = sU[r];
                a0 = fmaf(ur, pc0[r], a0);
                a1 = fmaf(ur, pc1[r], a1);
            }
            g_v[tid]       = a0;
            g_v[tid + 256] = a1;
            __syncthreads();
            // private release: one flag per consumer block, one writer thread
            if (tid < 128) red_rel_add(&g_flag_v_p[tid], 1);
        }
    } else {
        // ---- Psum[r, half]: blocks 64..127
        int p = blk - 64;
        int r = p >> 1;
        int o = (p & 1) * 256 + tid;
        const float* base = proj + (size_t)r * DD * OUT_DIM + o;
        float acc = 0.f;
        #pragma unroll
        for (int l = 0; l < DD; ++l) acc += base[l * OUT_DIM];
        g_Psum[r * OUT_DIM + o] = acc;
        __syncthreads();
        if (tid == 0) red_rel_add(&g_cnt_P, 1);
    }

    // ---- epilogue: out[b,o] = s[b]*v[o] + bias[o], 8 rows per block ----------
    // local s: warp w owns row blk*8+w; product of its 8 x-values then shfl-reduce
    float pr = (xa.x * xa.y) * (xa.z * xa.w) * ((xb.x * xb.y) * (xb.z * xb.w));
    #pragma unroll
    for (int off = 16; off; off >>= 1)
        pr *= __shfl_xor_sync(0xffffffffu, pr, off);
    if (lane == 0) sS[w] = pr;

    if (tid == 0) {                       // private flag: single poller
        while (ld_rlx(&g_flag_v_p[blk]) == 0) { }
        (void)ld_acq(&g_flag_v_p[blk]);
        st_relaxed(&g_flag_v_p[blk], 0);  // self-reset for next replay
    }
    __syncthreads();                      // sS ready + v visible

    float4 v = reinterpret_cast<const float4*>(g_v)[o4];
    float4* out4 = reinterpret_cast<float4*>(out);
    int sub = tid >> 7;                   // 0/1
    int b0 = blk * 8;
    #pragma unroll
    for (int i = 0; i < 4; ++i) {
        int row = 2 * i + sub;
        float s = sS[row];
        float4 o;
        o.x = fmaf(s, v.x, bi.x);
        o.y = fmaf(s, v.y, bi.y);
        o.z = fmaf(s, v.z, bi.z);
        o.w = fmaf(s, v.w, bi.w);
        out4[(size_t)(b0 + row) * 128 + o4] = o;
    }
}

// ---------------------------------------------------------------------------
extern "C" void kernel_launch(void* const* d_in, const int* in_sizes, int n_in,
                              void* d_out, int out_size) {
    const float* x     = (const float*)d_in[0];
    const float* cores = (const float*)d_in[1];
    const float* proj  = (const float*)d_in[2];
    const float* bias  = (const float*)d_in[3];
    float* out = (float*)d_out;

    fused_mps<<<128, 256>>>(x, cores, proj, bias, out);
}